// round 14
// baseline (speedup 1.0000x reference)
#include <cuda_runtime.h>
#include <math.h>

#define NN 10000
#define NE 40000
#define NG 128
#define VC 1584   // 32*48 kernel cols + 48 bias cols

// ---------------- scratch (static device globals; no runtime alloc) ----------
__device__ float g_a[NN * 32];
__device__ float g_e[NE * 32];
__device__ float g_s[NG * 16];
__device__ float g_v[NN * VC];      // 63.4 MB
__device__ float g_wt[48 * VC];     // transposed kernel+bias
__device__ float g_agg[NN * 48];
__device__ float g_asum[NG * 32];
__device__ float g_esum[NG * 32];
__device__ float g_wcat2[32 * 192]; // [We rows 80:112 | Ue]
__device__ float g_wcat3[32 * 288]; // [We rows 0:32 | We rows 32:64 | Un]
__device__ float g_pau[NN * 288];   // a @ wcat3
__device__ float g_s3[NG * 96];     // s @ We rows 64:80

__device__ __forceinline__ float sigm(float x) { return 1.f / (1.f + expf(-x)); }

__device__ __forceinline__ unsigned f2tf(float f) {
    unsigned u;
    asm("cvt.rna.tf32.f32 %0, %1;" : "=r"(u) : "f"(f));
    return u;
}
__device__ __forceinline__ void mma_tf32(float c[4],
                                         unsigned a0, unsigned a1,
                                         unsigned a2, unsigned a3,
                                         unsigned b0, unsigned b1) {
    asm volatile(
        "mma.sync.aligned.m16n8k8.row.col.f32.tf32.tf32.f32 "
        "{%0,%1,%2,%3}, {%4,%5,%6,%7}, {%8,%9}, {%0,%1,%2,%3};"
        : "+f"(c[0]), "+f"(c[1]), "+f"(c[2]), "+f"(c[3])
        : "r"(a0), "r"(a1), "r"(a2), "r"(a3), "r"(b0), "r"(b1));
}

// ---------------- weight prep ------------------------------------------------
__global__ void build_weights_kernel(const float* __restrict__ kern,
                                     const float* __restrict__ bias,
                                     const float* __restrict__ We,
                                     const float* __restrict__ Ue,
                                     const float* __restrict__ Un,
                                     float* __restrict__ wt,
                                     float* __restrict__ wcat2,
                                     float* __restrict__ wcat3) {
    int idx = blockIdx.x * blockDim.x + threadIdx.x;
    if (idx < 48 * VC) {
        int j = idx / VC, ki = idx % VC;
        wt[idx] = (ki < 1536) ? kern[ki * 48 + j] : bias[(ki - 1536) * 48 + j];
    }
    if (idx < 32 * 192) {
        int k = idx / 192, c = idx % 192;
        wcat2[idx] = (c < 96) ? We[(80 + k) * 96 + c] : Ue[k * 96 + (c - 96)];
    }
    if (idx < 32 * 288) {
        int k = idx / 288, c = idx % 288;
        float val;
        if (c < 96)       val = We[k * 96 + c];
        else if (c < 192) val = We[(32 + k) * 96 + (c - 96)];
        else              val = Un[k * 96 + (c - 192)];
        wcat3[idx] = val;
    }
}

// ---------------- fused v kernel: v = [a | s[agi]] @ wt (tf32, K=48) ---------
// Also zeroes agg. Block tile 64 x 128; 8 warps (4m x 2n).
__global__ __launch_bounds__(256)
void compute_v_fused(const float* __restrict__ a, const float* __restrict__ s,
                     const int* __restrict__ agi, const float* __restrict__ wt,
                     float* __restrict__ v, float* __restrict__ agg) {
    __shared__ __align__(16) char raw[(64 * 52 + 48 * 132) * 4];
    unsigned* sA = (unsigned*)raw;               // 64 x 52 (K=48 padded)
    unsigned* sB = (unsigned*)raw + 64 * 52;     // 48 x 132
    float* sC = (float*)raw;                     // 64 x 132 (reused)
    __shared__ int s_gi[64];
    int m0 = blockIdx.y * 64;
    int n0 = blockIdx.x * 128;
    int tid = threadIdx.x;

    // zero agg chunk (2041 blocks x 236 covers NN*48)
    {
        int bid = blockIdx.y * gridDim.x + blockIdx.x;
        int z = bid * 236 + tid;
        if (tid < 236 && z < NN * 48) agg[z] = 0.f;
    }

    if (tid < 64) s_gi[tid] = (m0 + tid < NN) ? agi[m0 + tid] : 0;
    __syncthreads();

    for (int i = tid; i < 64 * 32; i += 256) {
        int r = i >> 5, k = i & 31;
        float val = (m0 + r < NN) ? a[(size_t)(m0 + r) * 32 + k] : 0.f;
        sA[r * 52 + k] = f2tf(val);
    }
    for (int i = tid; i < 64 * 16; i += 256) {
        int r = i >> 4, k = i & 15;
        float val = (m0 + r < NN) ? s[s_gi[r] * 16 + k] : 0.f;
        sA[r * 52 + 32 + k] = f2tf(val);
    }
    for (int i = tid; i < 48 * 128; i += 256) {
        int k = i >> 7, n = i & 127;
        float val = (n0 + n < VC) ? wt[(size_t)k * VC + n0 + n] : 0.f;
        sB[k * 132 + n] = f2tf(val);
    }
    __syncthreads();

    int wid = tid >> 5, lane = tid & 31;
    int wm = wid & 3, wn = wid >> 2;
    int lq = lane >> 2, lr = lane & 3;

    float c[8][4];
#pragma unroll
    for (int nf = 0; nf < 8; nf++)
#pragma unroll
        for (int i = 0; i < 4; i++) c[nf][i] = 0.f;

#pragma unroll
    for (int ks = 0; ks < 6; ks++) {
        int ar = wm * 16 + lq;
        int ac = ks * 8 + lr;
        unsigned a0 = sA[ar * 52 + ac];
        unsigned a1 = sA[(ar + 8) * 52 + ac];
        unsigned a2 = sA[ar * 52 + ac + 4];
        unsigned a3 = sA[(ar + 8) * 52 + ac + 4];
#pragma unroll
        for (int nf = 0; nf < 8; nf++) {
            int bn = wn * 64 + nf * 8 + lq;
            unsigned b0 = sB[(ks * 8 + lr) * 132 + bn];
            unsigned b1 = sB[(ks * 8 + 4 + lr) * 132 + bn];
            mma_tf32(c[nf], a0, a1, a2, a3, b0, b1);
        }
    }
    __syncthreads();

    int row_l = wm * 16 + lq;
    int cb = wn * 64 + lr * 2;
#pragma unroll
    for (int nf = 0; nf < 8; nf++) {
        int col = cb + nf * 8;
        *(float2*)&sC[row_l * 132 + col] = make_float2(c[nf][0], c[nf][1]);
        *(float2*)&sC[(row_l + 8) * 132 + col] = make_float2(c[nf][2], c[nf][3]);
    }
    __syncthreads();

    for (int i = tid; i < 64 * 32; i += 256) {
        int r = i >> 5, c4 = i & 31;
        int row = m0 + r;
        int col = n0 + c4 * 4;
        if (row >= NN || col >= VC) continue;
        *(float4*)&v[(size_t)row * VC + col] = *(float4*)&sC[r * 132 + c4 * 4];
    }
}

// ---------------- pau GEMM + s3 + zero esum/asum -----------------------------
__global__ __launch_bounds__(288)
void pau_s3_kernel(const float* __restrict__ a, const float* __restrict__ W,
                   const float* __restrict__ Ws3, const float* __restrict__ s,
                   float* __restrict__ pau, float* __restrict__ s3,
                   float* __restrict__ esum, float* __restrict__ asum) {
    __shared__ float sW[32 * 288];
    __shared__ __align__(16) float sx[16 * 32];
    int tid = threadIdx.x;
    int bid = blockIdx.x;

    if (bid < 32 && tid < 256) {
        int z = bid * 256 + tid;
        if (z < NG * 32) esum[z] = 0.f;
        else asum[z - NG * 32] = 0.f;
    }

    if (bid == 625) {
        for (int i = tid; i < NG * 16; i += 288) sW[i] = s[i];
        __syncthreads();
        if (tid < 96) {
            for (int g = 0; g < NG; g++) {
                float acc = 0.f;
#pragma unroll
                for (int k = 0; k < 16; k++) acc += sW[g * 16 + k] * Ws3[k * 96 + tid];
                s3[g * 96 + tid] = acc;
            }
        }
        return;
    }

    int base = bid * 16;
#pragma unroll
    for (int k = 0; k < 32; k++) sW[k * 288 + tid] = W[k * 288 + tid];
    for (int i = tid; i < 16 * 32; i += 288) sx[i] = a[(size_t)base * 32 + i];
    __syncthreads();

    float acc[16];
#pragma unroll
    for (int r = 0; r < 16; r++) acc[r] = 0.f;
    const float4* sx4 = (const float4*)sx;
#pragma unroll
    for (int k4 = 0; k4 < 8; k4++) {
        float w0 = sW[(4 * k4 + 0) * 288 + tid];
        float w1 = sW[(4 * k4 + 1) * 288 + tid];
        float w2 = sW[(4 * k4 + 2) * 288 + tid];
        float w3 = sW[(4 * k4 + 3) * 288 + tid];
#pragma unroll
        for (int r = 0; r < 16; r++) {
            float4 xv = sx4[r * 8 + k4];
            acc[r] += w0 * xv.x; acc[r] += w1 * xv.y;
            acc[r] += w2 * xv.z; acc[r] += w3 * xv.w;
        }
    }
#pragma unroll
    for (int r = 0; r < 16; r++)
        pau[(size_t)(base + r) * 288 + tid] = acc[r];
}

// ---------------- fused edge kernel: ew MMA + GRU finalize -------------------
// Block: 64 edges. __launch_bounds__(256,3): cap regs at 85 so 3 blocks/SM fit
// the regfile (90 regs capped occupancy at 2 blocks = 25% in R13).
__global__ __launch_bounds__(256, 3)
void edge_fused_kernel(const float* __restrict__ e_in,
                       const float* __restrict__ W,
                       const int* __restrict__ pair,
                       const int* __restrict__ bgi,
                       const float* __restrict__ pau,
                       const float* __restrict__ s3,
                       const float* __restrict__ bin,
                       const float* __restrict__ brec,
                       float* __restrict__ e_out,
                       float* __restrict__ esum) {
    extern __shared__ __align__(16) char dynsm[];
    unsigned* sA = (unsigned*)dynsm;               // 64*33
    unsigned* sB = (unsigned*)dynsm + 64 * 33;     // 32*196
    float* sC = (float*)dynsm;                     // 64*196 (reused)
    __shared__ int sSrc[64], sDst[64], sBg[64];
    int m0 = blockIdx.x * 64;
    int tid = threadIdx.x;

    for (int i = tid; i < 64 * 32; i += 256) {
        int r = i >> 5, k = i & 31;
        sA[r * 33 + k] = f2tf(e_in[(size_t)(m0 + r) * 32 + k]);
    }
    for (int i = tid; i < 32 * 192; i += 256) {
        int k = i / 192, n = i % 192;
        sB[k * 196 + n] = f2tf(W[k * 192 + n]);
    }
    if (tid < 64) {
        int e = m0 + tid;
        sSrc[tid] = pair[2 * e];
        sDst[tid] = pair[2 * e + 1];
        sBg[tid]  = bgi[e];
    }
    __syncthreads();

    int wid = tid >> 5, lane = tid & 31;
    int wm = wid & 3, wn = wid >> 2;
    int lq = lane >> 2, lr = lane & 3;

    float c[12][4];
#pragma unroll
    for (int nf = 0; nf < 12; nf++)
#pragma unroll
        for (int i = 0; i < 4; i++) c[nf][i] = 0.f;

#pragma unroll
    for (int ks = 0; ks < 4; ks++) {
        int ar = wm * 16 + lq;
        int ac = ks * 8 + lr;
        unsigned a0 = sA[ar * 33 + ac];
        unsigned a1 = sA[(ar + 8) * 33 + ac];
        unsigned a2 = sA[ar * 33 + ac + 4];
        unsigned a3 = sA[(ar + 8) * 33 + ac + 4];
#pragma unroll
        for (int nf = 0; nf < 12; nf++) {
            int bn = wn * 96 + nf * 8 + lq;
            unsigned b0 = sB[(ks * 8 + lr) * 196 + bn];
            unsigned b1 = sB[(ks * 8 + 4 + lr) * 196 + bn];
            mma_tf32(c[nf], a0, a1, a2, a3, b0, b1);
        }
    }
    __syncthreads();

    int row_l = wm * 16 + lq;
#pragma unroll
    for (int nf = 0; nf < 12; nf++) {
        int col = wn * 96 + nf * 8 + lr * 2;
        *(float2*)&sC[row_l * 196 + col] = make_float2(c[nf][0], c[nf][1]);
        *(float2*)&sC[(row_l + 8) * 196 + col] = make_float2(c[nf][2], c[nf][3]);
    }
    __syncthreads();

    for (int idx = tid; idx < 64 * 32; idx += 256) {
        int el = idx >> 5, j = idx & 31;
        int e = m0 + el;
        int src = sSrc[el], dst = sDst[el], g = sBg[el];
        const float* pA = pau + (size_t)src * 288;
        const float* pB = pau + (size_t)dst * 288 + 96;
        const float* pS = s3 + g * 96;
        const float* pE = sC + el * 196;
        float xz = pA[j]      + pB[j]      + pS[j]      + pE[j]      + bin[j];
        float xr = pA[32 + j] + pB[32 + j] + pS[32 + j] + pE[32 + j] + bin[32 + j];
        float xh = pA[64 + j] + pB[64 + j] + pS[64 + j] + pE[64 + j] + bin[64 + j];
        float hz = pE[96 + j]  + brec[j];
        float hr = pE[128 + j] + brec[32 + j];
        float hh = pE[160 + j] + brec[64 + j];
        float h  = e_in[(size_t)e * 32 + j];
        float z  = sigm(xz + hz);
        float r  = sigm(xr + hr);
        float hc = tanhf(xh + r * hh);
        float val = z * h + (1.f - z) * hc;
        e_out[(size_t)e * 32 + j] = val;
        atomicAdd(&esum[g * 32 + j], val);
    }
}

// ---------------- per-edge message + scatter-add by src (src-run dedup) ------
#define EPW 8
__global__ __launch_bounds__(256)
void scatter_kernel(const float* __restrict__ e_feat,
                    const int* __restrict__ pair,
                    const float* __restrict__ v,
                    float* __restrict__ agg) {
    int lane = threadIdx.x & 31;
    int warp = (blockIdx.x * blockDim.x + threadIdx.x) >> 5;
    int e0 = warp * EPW;
    if (e0 >= NE) return;
    int eend = min(e0 + EPW, NE);
    int cur_src = __ldg(&pair[2 * e0]);
    float acc0 = 0.f, acc1 = 0.f;
    for (int e = e0; e < eend; e++) {
        int src = __ldg(&pair[2 * e]);
        int dst = __ldg(&pair[2 * e + 1]);
        if (src != cur_src) {
            atomicAdd(&agg[cur_src * 48 + lane], acc0);
            if (lane < 16) atomicAdd(&agg[cur_src * 48 + 32 + lane], acc1);
            acc0 = 0.f; acc1 = 0.f; cur_src = src;
        }
        const float* vp = v + (size_t)dst * VC;
        float ev = __ldg(&e_feat[(size_t)e * 32 + lane]);
        acc0 += __ldg(&vp[1536 + lane]);
        if (lane < 16) acc1 += __ldg(&vp[1568 + lane]);
#pragma unroll
        for (int k = 0; k < 32; k++) {
            float ek = __shfl_sync(0xffffffffu, ev, k);
            acc0 += ek * __ldg(&vp[k * 48 + lane]);
            if (lane < 16) acc1 += ek * __ldg(&vp[k * 48 + 32 + lane]);
        }
    }
    atomicAdd(&agg[cur_src * 48 + lane], acc0);
    if (lane < 16) atomicAdd(&agg[cur_src * 48 + 32 + lane], acc1);
}

// ---------------- fused node kernel: agg@Wn GEMM + GRU finalize --------------
__global__ __launch_bounds__(96)
void node_fused_kernel(const float* __restrict__ agg,
                       const float* __restrict__ Wn,
                       const float* __restrict__ pau,
                       const float* __restrict__ a_in,
                       const int* __restrict__ agi,
                       const float* __restrict__ bin,
                       const float* __restrict__ brec,
                       float* __restrict__ a_out,
                       float* __restrict__ asum) {
    __shared__ float sW[48 * 96];
    __shared__ __align__(16) float sx[16 * 48];
    __shared__ float sxw[16 * 96];
    __shared__ int sgi[16];
    int tid = threadIdx.x;
    int base = blockIdx.x * 16;

    for (int i = tid; i < 48 * 96; i += 96) sW[i] = Wn[i];
    for (int i = tid; i < 16 * 48; i += 96) sx[i] = agg[(size_t)base * 48 + i];
    if (tid < 16) sgi[tid] = agi[base + tid];
    __syncthreads();

    float acc[16];
#pragma unroll
    for (int r = 0; r < 16; r++) acc[r] = 0.f;
    const float4* sx4 = (const float4*)sx;
#pragma unroll
    for (int k4 = 0; k4 < 12; k4++) {
        float w0 = sW[(4 * k4 + 0) * 96 + tid];
        float w1 = sW[(4 * k4 + 1) * 96 + tid];
        float w2 = sW[(4 * k4 + 2) * 96 + tid];
        float w3 = sW[(4 * k4 + 3) * 96 + tid];
#pragma unroll
        for (int r = 0; r < 16; r++) {
            float4 xv = sx4[r * 12 + k4];
            acc[r] += w0 * xv.x; acc[r] += w1 * xv.y;
            acc[r] += w2 * xv.z; acc[r] += w3 * xv.w;
        }
    }
#pragma unroll
    for (int r = 0; r < 16; r++) sxw[r * 96 + tid] = acc[r];
    __syncthreads();

    for (int idx = tid; idx < 16 * 32; idx += 96) {
        int nl = idx >> 5, j = idx & 31;
        int n = base + nl;
        const float* pH = pau + (size_t)n * 288 + 192;
        float xz = sxw[nl * 96 + j]      + bin[j];
        float xr = sxw[nl * 96 + 32 + j] + bin[32 + j];
        float xh = sxw[nl * 96 + 64 + j] + bin[64 + j];
        float hz = pH[j]      + brec[j];
        float hr = pH[32 + j] + brec[32 + j];
        float hh = pH[64 + j] + brec[64 + j];
        float h  = a_in[(size_t)n * 32 + j];
        float z  = sigm(xz + hz);
        float r  = sigm(xr + hr);
        float hc = tanhf(xh + r * hh);
        float val = z * h + (1.f - z) * hc;
        a_out[(size_t)n * 32 + j] = val;
        atomicAdd(&asum[sgi[nl] * 32 + j], val);
    }
}

// ---------------- state GRU: s = GRU([asum, esum, s], s) ---------------------
__global__ void state_gru_kernel(
    const float* __restrict__ asum, const float* __restrict__ esum,
    const float* __restrict__ s_in,
    const float* __restrict__ Ws, const float* __restrict__ Us,
    const float* __restrict__ bsin, const float* __restrict__ bsrec,
    float* __restrict__ s_out) {
    __shared__ float sx[80];
    __shared__ float shh[16];
    __shared__ float sxw[48];
    __shared__ float shu[48];
    int g = blockIdx.x;
    int c = threadIdx.x;  // 80
    if (c < 32)      sx[c] = asum[g * 32 + c];
    else if (c < 64) sx[c] = esum[g * 32 + (c - 32)];
    else             sx[c] = s_in[g * 16 + (c - 64)];
    if (c < 16) shh[c] = s_in[g * 16 + c];
    __syncthreads();
    if (c < 48) {
        float xw = bsin[c], hu = bsrec[c];
        for (int k = 0; k < 80; k++) xw += sx[k] * Ws[k * 48 + c];
        for (int k = 0; k < 16; k++) hu += shh[k] * Us[k * 48 + c];
        sxw[c] = xw; shu[c] = hu;
    }
    __syncthreads();
    if (c < 16) {
        float z = sigm(sxw[c] + shu[c]);
        float r = sigm(sxw[16 + c] + shu[16 + c]);
        float hc = tanhf(sxw[32 + c] + r * shu[32 + c]);
        s_out[g * 16 + c] = z * shh[c] + (1.f - z) * hc;
    }
}

// ---------------- host orchestration -----------------------------------------
extern "C" void kernel_launch(void* const* d_in, const int* in_sizes, int n_in,
                              void* d_out, int out_size) {
    const float* a0    = (const float*)d_in[0];
    const float* e0    = (const float*)d_in[1];
    const float* s0    = (const float*)d_in[2];
    const int*   pair  = (const int*)d_in[3];
    const int*   agi   = (const int*)d_in[4];
    const int*   bgi   = (const int*)d_in[5];
    const float* kern  = (const float*)d_in[6];
    const float* bias  = (const float*)d_in[7];
    const float* We    = (const float*)d_in[8];
    const float* Ue    = (const float*)d_in[9];
    const float* bein  = (const float*)d_in[10];
    const float* berec = (const float*)d_in[11];
    const float* Wn    = (const float*)d_in[12];
    const float* Un    = (const float*)d_in[13];
    const float* bnin  = (const float*)d_in[14];
    const float* bnrec = (const float*)d_in[15];
    const float* Ws    = (const float*)d_in[16];
    const float* Us    = (const float*)d_in[17];
    const float* bsin  = (const float*)d_in[18];
    const float* bsrec = (const float*)d_in[19];
    float* out = (float*)d_out;

    float *ga, *ge, *gs, *gv, *gwt, *gagg, *gas, *ges;
    float *gw2, *gw3, *gpau, *gs3;
    cudaGetSymbolAddress((void**)&ga,    g_a);
    cudaGetSymbolAddress((void**)&ge,    g_e);
    cudaGetSymbolAddress((void**)&gs,    g_s);
    cudaGetSymbolAddress((void**)&gv,    g_v);
    cudaGetSymbolAddress((void**)&gwt,   g_wt);
    cudaGetSymbolAddress((void**)&gagg,  g_agg);
    cudaGetSymbolAddress((void**)&gas,   g_asum);
    cudaGetSymbolAddress((void**)&ges,   g_esum);
    cudaGetSymbolAddress((void**)&gw2,   g_wcat2);
    cudaGetSymbolAddress((void**)&gw3,   g_wcat3);
    cudaGetSymbolAddress((void**)&gpau,  g_pau);
    cudaGetSymbolAddress((void**)&gs3,   g_s3);

    static bool s_init = false;
    static cudaStream_t st2;
    static cudaEvent_t ev0[2], evE[2];
    const int EDGE_SMEM = 64 * 196 * 4;   // 50176 bytes
    if (!s_init) {
        cudaStreamCreateWithFlags(&st2, cudaStreamNonBlocking);
        for (int i = 0; i < 2; i++) {
            cudaEventCreateWithFlags(&ev0[i], cudaEventDisableTiming);
            cudaEventCreateWithFlags(&evE[i], cudaEventDisableTiming);
        }
        cudaFuncSetAttribute(edge_fused_kernel,
                             cudaFuncAttributeMaxDynamicSharedMemorySize, EDGE_SMEM);
        s_init = true;
    }

    build_weights_kernel<<<(48 * VC + 255) / 256, 256>>>(kern, bias, We, Ue, Un,
                                                         gwt, gw2, gw3);

    float* oa[2] = {ga, out};
    float* oe[2] = {ge, out + NN * 32};
    float* os[2] = {gs, out + NN * 32 + NE * 32};
    const float* ia = a0;
    const float* ie = e0;
    const float* is_ = s0;

    for (int step = 0; step < 2; step++) {
        cudaEventRecord(ev0[step], 0);

        // main: fused v GEMM (also zeroes agg)
        compute_v_fused<<<dim3((VC + 127) / 128, (NN + 63) / 64), 256>>>(
            ia, is_, agi, gwt, gv, gagg);

        // st2: pau+s3 (+zero esum/asum), then fused edge MMA+GRU
        cudaStreamWaitEvent(st2, ev0[step], 0);
        pau_s3_kernel<<<626, 288, 0, st2>>>(ia, gw3, We + 64 * 96, is_,
                                            gpau, gs3, ges, gas);
        edge_fused_kernel<<<NE / 64, 256, EDGE_SMEM, st2>>>(
            ie, gw2, pair, bgi, gpau, gs3, bein, berec, oe[step], ges);
        cudaEventRecord(evE[step], st2);

        // main: join, scatter, fused node GRU, state GRU
        cudaStreamWaitEvent(0, evE[step], 0);
        scatter_kernel<<<(NE / EPW + 7) / 8, 256>>>(oe[step], pair, gv, gagg);
        node_fused_kernel<<<NN / 16, 96>>>(gagg, Wn, gpau, ia, agi,
                                           bnin, bnrec, oa[step], gas);
        state_gru_kernel<<<NG, 80>>>(gas, ges, is_, Ws, Us, bsin, bsrec, os[step]);

        ia = oa[step]; ie = oe[step]; is_ = os[step];
    }
}

// round 16
// speedup vs baseline: 1.2589x; 1.2589x over previous
#include <cuda_runtime.h>
#include <math.h>

#define NN 10000
#define NE 40000
#define NG 128
#define VC 1584   // 32*48 kernel cols + 48 bias cols
#define NBV 2041  // 157 * 13 v-tiles
#define NBP 626   // pau blocks (625) + s3 block (1)

// ---------------- scratch (static device globals; no runtime alloc) ----------
__device__ float    g_a[NN * 32];
__device__ float    g_e[NE * 32];
__device__ float    g_s[NG * 16];
__device__ float    g_v[NN * VC];      // 63.4 MB
__device__ unsigned g_wt32[48 * VC];   // transposed kernel+bias, tf32 bits
__device__ float    g_agg[NN * 48];
__device__ float    g_asum[NG * 32];
__device__ float    g_esum[NG * 32];
__device__ unsigned g_wcat2[32 * 192]; // [We rows 80:112 | Ue], tf32 bits
__device__ float    g_wcat3[32 * 288]; // [We rows 0:32 | We rows 32:64 | Un]
__device__ float    g_pau[NN * 288];   // a @ wcat3
__device__ float    g_s3[NG * 96];     // s @ We rows 64:80

__device__ __forceinline__ float sigm(float x) { return 1.f / (1.f + expf(-x)); }

__device__ __forceinline__ unsigned f2tf(float f) {
    unsigned u;
    asm("cvt.rna.tf32.f32 %0, %1;" : "=r"(u) : "f"(f));
    return u;
}
__device__ __forceinline__ void mma_tf32(float c[4],
                                         unsigned a0, unsigned a1,
                                         unsigned a2, unsigned a3,
                                         unsigned b0, unsigned b1) {
    asm volatile(
        "mma.sync.aligned.m16n8k8.row.col.f32.tf32.tf32.f32 "
        "{%0,%1,%2,%3}, {%4,%5,%6,%7}, {%8,%9}, {%0,%1,%2,%3};"
        : "+f"(c[0]), "+f"(c[1]), "+f"(c[2]), "+f"(c[3])
        : "r"(a0), "r"(a1), "r"(a2), "r"(a3), "r"(b0), "r"(b1));
}

// ---------------- weight prep (tf32 pre-conversion for MMA consumers) --------
__global__ void build_weights_kernel(const float* __restrict__ kern,
                                     const float* __restrict__ bias,
                                     const float* __restrict__ We,
                                     const float* __restrict__ Ue,
                                     const float* __restrict__ Un,
                                     unsigned* __restrict__ wt32,
                                     unsigned* __restrict__ wcat2,
                                     float* __restrict__ wcat3) {
    int idx = blockIdx.x * blockDim.x + threadIdx.x;
    if (idx < 48 * VC) {
        int j = idx / VC, ki = idx % VC;
        float val = (ki < 1536) ? kern[ki * 48 + j] : bias[(ki - 1536) * 48 + j];
        wt32[idx] = f2tf(val);
    }
    if (idx < 32 * 192) {
        int k = idx / 192, c = idx % 192;
        wcat2[idx] = f2tf((c < 96) ? We[(80 + k) * 96 + c] : Ue[k * 96 + (c - 96)]);
    }
    if (idx < 32 * 288) {
        int k = idx / 288, c = idx % 288;
        float val;
        if (c < 96)       val = We[k * 96 + c];
        else if (c < 192) val = We[(32 + k) * 96 + (c - 96)];
        else              val = Un[k * 96 + (c - 192)];
        wcat3[idx] = val;
    }
}

// ---------------- front kernel: v MMA tiles + pau GEMM + s3 + zeroing --------
// blocks [0, NBV): v = [a | s[agi]] @ wt (tf32, K=48), tile 64x128, + zero agg.
// blocks [NBV, NBV+625): pau = a @ wcat3 (16-row tiles); first 32 also zero
// esum/asum. block NBV+625: s3 = s @ We[64:80].
__global__ __launch_bounds__(288)
void front_kernel(const float* __restrict__ a, const float* __restrict__ s,
                  const int* __restrict__ agi, const unsigned* __restrict__ wt32,
                  float* __restrict__ v, float* __restrict__ agg,
                  const float* __restrict__ W3, const float* __restrict__ Ws3,
                  float* __restrict__ pau, float* __restrict__ s3,
                  float* __restrict__ esum, float* __restrict__ asum) {
    __shared__ __align__(16) char raw[39680];
    __shared__ int s_gi[64];
    int tid = threadIdx.x;
    int b = blockIdx.x;

    if (b >= NBV) {
        // ---------------- pau / s3 part ----------------
        float* sW = (float*)raw;                       // 32*288
        float* sx = (float*)raw + 32 * 288;            // 16*32
        int bid = b - NBV;

        if (bid < 32 && tid < 256) {
            int z = bid * 256 + tid;
            if (z < NG * 32) esum[z] = 0.f;
            else asum[z - NG * 32] = 0.f;
        }
        if (bid == 625) {
            for (int i = tid; i < NG * 16; i += 288) sW[i] = s[i];
            __syncthreads();
            if (tid < 96) {
                for (int g = 0; g < NG; g++) {
                    float acc = 0.f;
#pragma unroll
                    for (int k = 0; k < 16; k++)
                        acc += sW[g * 16 + k] * Ws3[k * 96 + tid];
                    s3[g * 96 + tid] = acc;
                }
            }
            return;
        }

        int base = bid * 16;
#pragma unroll
        for (int k = 0; k < 32; k++) sW[k * 288 + tid] = W3[k * 288 + tid];
        for (int i = tid; i < 16 * 32; i += 288) sx[i] = a[(size_t)base * 32 + i];
        __syncthreads();

        float acc[16];
#pragma unroll
        for (int r = 0; r < 16; r++) acc[r] = 0.f;
        const float4* sx4 = (const float4*)sx;
#pragma unroll
        for (int k4 = 0; k4 < 8; k4++) {
            float w0 = sW[(4 * k4 + 0) * 288 + tid];
            float w1 = sW[(4 * k4 + 1) * 288 + tid];
            float w2 = sW[(4 * k4 + 2) * 288 + tid];
            float w3 = sW[(4 * k4 + 3) * 288 + tid];
#pragma unroll
            for (int r = 0; r < 16; r++) {
                float4 xv = sx4[r * 8 + k4];
                acc[r] += w0 * xv.x; acc[r] += w1 * xv.y;
                acc[r] += w2 * xv.z; acc[r] += w3 * xv.w;
            }
        }
#pragma unroll
        for (int r = 0; r < 16; r++)
            pau[(size_t)(base + r) * 288 + tid] = acc[r];
        return;
    }

    // ---------------- v part ----------------
    unsigned* sA = (unsigned*)raw;               // 64 x 52
    unsigned* sB = (unsigned*)raw + 64 * 52;     // 48 x 132
    float* sC = (float*)raw;                     // 64 x 132 (reused)
    int m0 = (b / 13) * 64;
    int n0 = (b % 13) * 128;

    {   // zero agg chunk: 2041 blocks x 236 covers NN*48
        int z = b * 236 + tid;
        if (tid < 236 && z < NN * 48) agg[z] = 0.f;
    }
    if (tid < 64) s_gi[tid] = (m0 + tid < NN) ? agi[m0 + tid] : 0;
    __syncthreads();

    for (int i = tid; i < 64 * 32; i += 288) {
        int r = i >> 5, k = i & 31;
        float val = (m0 + r < NN) ? a[(size_t)(m0 + r) * 32 + k] : 0.f;
        sA[r * 52 + k] = f2tf(val);
    }
    for (int i = tid; i < 64 * 16; i += 288) {
        int r = i >> 4, k = i & 15;
        float val = (m0 + r < NN) ? s[s_gi[r] * 16 + k] : 0.f;
        sA[r * 52 + 32 + k] = f2tf(val);
    }
    for (int i = tid; i < 48 * 128; i += 288) {
        int k = i >> 7, n = i & 127;
        sB[k * 132 + n] = (n0 + n < VC) ? wt32[(size_t)k * VC + n0 + n] : 0u;
    }
    __syncthreads();

    int wid = tid >> 5, lane = tid & 31;
    float c[8][4];
    int row_l = 0, cb = 0;
    if (wid < 8) {
        int wm = wid & 3, wn = wid >> 2;
        int lq = lane >> 2, lr = lane & 3;
#pragma unroll
        for (int nf = 0; nf < 8; nf++)
#pragma unroll
            for (int i = 0; i < 4; i++) c[nf][i] = 0.f;
#pragma unroll
        for (int ks = 0; ks < 6; ks++) {
            int ar = wm * 16 + lq;
            int ac = ks * 8 + lr;
            unsigned a0 = sA[ar * 52 + ac];
            unsigned a1 = sA[(ar + 8) * 52 + ac];
            unsigned a2 = sA[ar * 52 + ac + 4];
            unsigned a3 = sA[(ar + 8) * 52 + ac + 4];
#pragma unroll
            for (int nf = 0; nf < 8; nf++) {
                int bn = wn * 64 + nf * 8 + lq;
                unsigned b0 = sB[(ks * 8 + lr) * 132 + bn];
                unsigned b1 = sB[(ks * 8 + 4 + lr) * 132 + bn];
                mma_tf32(c[nf], a0, a1, a2, a3, b0, b1);
            }
        }
        row_l = wm * 16 + lq;
        cb = wn * 64 + lr * 2;
    }
    __syncthreads();

    if (wid < 8) {
#pragma unroll
        for (int nf = 0; nf < 8; nf++) {
            int col = cb + nf * 8;
            *(float2*)&sC[row_l * 132 + col] = make_float2(c[nf][0], c[nf][1]);
            *(float2*)&sC[(row_l + 8) * 132 + col] = make_float2(c[nf][2], c[nf][3]);
        }
    }
    __syncthreads();

    for (int i = tid; i < 64 * 32; i += 288) {
        int r = i >> 5, c4 = i & 31;
        int row = m0 + r;
        int col = n0 + c4 * 4;
        if (row >= NN || col >= VC) continue;
        *(float4*)&v[(size_t)row * VC + col] = *(float4*)&sC[r * 132 + c4 * 4];
    }
}

// ---------------- fused edge kernel: ew MMA + GRU finalize -------------------
__global__ __launch_bounds__(256)
void edge_fused_kernel(const float* __restrict__ e_in,
                       const unsigned* __restrict__ W,
                       const int* __restrict__ pair,
                       const int* __restrict__ bgi,
                       const float* __restrict__ pau,
                       const float* __restrict__ s3,
                       const float* __restrict__ bin,
                       const float* __restrict__ brec,
                       float* __restrict__ e_out,
                       float* __restrict__ esum) {
    extern __shared__ __align__(16) char dynsm[];
    unsigned* sA = (unsigned*)dynsm;               // 64*33
    unsigned* sB = (unsigned*)dynsm + 64 * 33;     // 32*196
    float* sC = (float*)dynsm;                     // 64*196 (reused)
    __shared__ int sSrc[64], sDst[64], sBg[64];
    int m0 = blockIdx.x * 64;
    int tid = threadIdx.x;

    for (int i = tid; i < 64 * 32; i += 256) {
        int r = i >> 5, k = i & 31;
        sA[r * 33 + k] = f2tf(e_in[(size_t)(m0 + r) * 32 + k]);
    }
    for (int i = tid; i < 32 * 192; i += 256) {
        int k = i / 192, n = i % 192;
        sB[k * 196 + n] = W[k * 192 + n];
    }
    if (tid < 64) {
        int e = m0 + tid;
        sSrc[tid] = pair[2 * e];
        sDst[tid] = pair[2 * e + 1];
        sBg[tid]  = bgi[e];
    }
    __syncthreads();

    int wid = tid >> 5, lane = tid & 31;
    int wm = wid & 3, wn = wid >> 2;
    int lq = lane >> 2, lr = lane & 3;

    float c[12][4];
#pragma unroll
    for (int nf = 0; nf < 12; nf++)
#pragma unroll
        for (int i = 0; i < 4; i++) c[nf][i] = 0.f;

#pragma unroll
    for (int ks = 0; ks < 4; ks++) {
        int ar = wm * 16 + lq;
        int ac = ks * 8 + lr;
        unsigned a0 = sA[ar * 33 + ac];
        unsigned a1 = sA[(ar + 8) * 33 + ac];
        unsigned a2 = sA[ar * 33 + ac + 4];
        unsigned a3 = sA[(ar + 8) * 33 + ac + 4];
#pragma unroll
        for (int nf = 0; nf < 12; nf++) {
            int bn = wn * 96 + nf * 8 + lq;
            unsigned b0 = sB[(ks * 8 + lr) * 196 + bn];
            unsigned b1 = sB[(ks * 8 + 4 + lr) * 196 + bn];
            mma_tf32(c[nf], a0, a1, a2, a3, b0, b1);
        }
    }
    __syncthreads();

    int row_l = wm * 16 + lq;
#pragma unroll
    for (int nf = 0; nf < 12; nf++) {
        int col = wn * 96 + nf * 8 + lr * 2;
        *(float2*)&sC[row_l * 196 + col] = make_float2(c[nf][0], c[nf][1]);
        *(float2*)&sC[(row_l + 8) * 196 + col] = make_float2(c[nf][2], c[nf][3]);
    }
    __syncthreads();

    for (int idx = tid; idx < 64 * 32; idx += 256) {
        int el = idx >> 5, j = idx & 31;
        int e = m0 + el;
        int src = sSrc[el], dst = sDst[el], g = sBg[el];
        const float* pA = pau + (size_t)src * 288;
        const float* pB = pau + (size_t)dst * 288 + 96;
        const float* pS = s3 + g * 96;
        const float* pE = sC + el * 196;
        float xz = pA[j]      + pB[j]      + pS[j]      + pE[j]      + bin[j];
        float xr = pA[32 + j] + pB[32 + j] + pS[32 + j] + pE[32 + j] + bin[32 + j];
        float xh = pA[64 + j] + pB[64 + j] + pS[64 + j] + pE[64 + j] + bin[64 + j];
        float hz = pE[96 + j]  + brec[j];
        float hr = pE[128 + j] + brec[32 + j];
        float hh = pE[160 + j] + brec[64 + j];
        float h  = e_in[(size_t)e * 32 + j];
        float z  = sigm(xz + hz);
        float r  = sigm(xr + hr);
        float hc = tanhf(xh + r * hh);
        float val = z * h + (1.f - z) * hc;
        e_out[(size_t)e * 32 + j] = val;
        atomicAdd(&esum[g * 32 + j], val);
    }
}

// ---------------- per-edge message + scatter-add by src (src-run dedup) ------
#define EPW 8
__global__ __launch_bounds__(256)
void scatter_kernel(const float* __restrict__ e_feat,
                    const int* __restrict__ pair,
                    const float* __restrict__ v,
                    float* __restrict__ agg) {
    int lane = threadIdx.x & 31;
    int warp = (blockIdx.x * blockDim.x + threadIdx.x) >> 5;
    int e0 = warp * EPW;
    if (e0 >= NE) return;
    int eend = min(e0 + EPW, NE);
    int cur_src = __ldg(&pair[2 * e0]);
    float acc0 = 0.f, acc1 = 0.f;
    for (int e = e0; e < eend; e++) {
        int src = __ldg(&pair[2 * e]);
        int dst = __ldg(&pair[2 * e + 1]);
        if (src != cur_src) {
            atomicAdd(&agg[cur_src * 48 + lane], acc0);
            if (lane < 16) atomicAdd(&agg[cur_src * 48 + 32 + lane], acc1);
            acc0 = 0.f; acc1 = 0.f; cur_src = src;
        }
        const float* vp = v + (size_t)dst * VC;
        float ev = __ldg(&e_feat[(size_t)e * 32 + lane]);
        acc0 += __ldg(&vp[1536 + lane]);
        if (lane < 16) acc1 += __ldg(&vp[1568 + lane]);
#pragma unroll
        for (int k = 0; k < 32; k++) {
            float ek = __shfl_sync(0xffffffffu, ev, k);
            acc0 += ek * __ldg(&vp[k * 48 + lane]);
            if (lane < 16) acc1 += ek * __ldg(&vp[k * 48 + 32 + lane]);
        }
    }
    atomicAdd(&agg[cur_src * 48 + lane], acc0);
    if (lane < 16) atomicAdd(&agg[cur_src * 48 + 32 + lane], acc1);
}

// ---------------- fused node kernel: agg@Wn GEMM + GRU finalize --------------
__global__ __launch_bounds__(96)
void node_fused_kernel(const float* __restrict__ agg,
                       const float* __restrict__ Wn,
                       const float* __restrict__ pau,
                       const float* __restrict__ a_in,
                       const int* __restrict__ agi,
                       const float* __restrict__ bin,
                       const float* __restrict__ brec,
                       float* __restrict__ a_out,
                       float* __restrict__ asum) {
    __shared__ float sW[48 * 96];
    __shared__ __align__(16) float sx[16 * 48];
    __shared__ float sxw[16 * 96];
    __shared__ int sgi[16];
    int tid = threadIdx.x;
    int base = blockIdx.x * 16;

    for (int i = tid; i < 48 * 96; i += 96) sW[i] = Wn[i];
    for (int i = tid; i < 16 * 48; i += 96) sx[i] = agg[(size_t)base * 48 + i];
    if (tid < 16) sgi[tid] = agi[base + tid];
    __syncthreads();

    float acc[16];
#pragma unroll
    for (int r = 0; r < 16; r++) acc[r] = 0.f;
    const float4* sx4 = (const float4*)sx;
#pragma unroll
    for (int k4 = 0; k4 < 12; k4++) {
        float w0 = sW[(4 * k4 + 0) * 96 + tid];
        float w1 = sW[(4 * k4 + 1) * 96 + tid];
        float w2 = sW[(4 * k4 + 2) * 96 + tid];
        float w3 = sW[(4 * k4 + 3) * 96 + tid];
#pragma unroll
        for (int r = 0; r < 16; r++) {
            float4 xv = sx4[r * 12 + k4];
            acc[r] += w0 * xv.x; acc[r] += w1 * xv.y;
            acc[r] += w2 * xv.z; acc[r] += w3 * xv.w;
        }
    }
#pragma unroll
    for (int r = 0; r < 16; r++) sxw[r * 96 + tid] = acc[r];
    __syncthreads();

    for (int idx = tid; idx < 16 * 32; idx += 96) {
        int nl = idx >> 5, j = idx & 31;
        int n = base + nl;
        const float* pH = pau + (size_t)n * 288 + 192;
        float xz = sxw[nl * 96 + j]      + bin[j];
        float xr = sxw[nl * 96 + 32 + j] + bin[32 + j];
        float xh = sxw[nl * 96 + 64 + j] + bin[64 + j];
        float hz = pH[j]      + brec[j];
        float hr = pH[32 + j] + brec[32 + j];
        float hh = pH[64 + j] + brec[64 + j];
        float h  = a_in[(size_t)n * 32 + j];
        float z  = sigm(xz + hz);
        float r  = sigm(xr + hr);
        float hc = tanhf(xh + r * hh);
        float val = z * h + (1.f - z) * hc;
        a_out[(size_t)n * 32 + j] = val;
        atomicAdd(&asum[sgi[nl] * 32 + j], val);
    }
}

// ---------------- state GRU: s = GRU([asum, esum, s], s) ---------------------
__global__ void state_gru_kernel(
    const float* __restrict__ asum, const float* __restrict__ esum,
    const float* __restrict__ s_in,
    const float* __restrict__ Ws, const float* __restrict__ Us,
    const float* __restrict__ bsin, const float* __restrict__ bsrec,
    float* __restrict__ s_out) {
    __shared__ float sx[80];
    __shared__ float shh[16];
    __shared__ float sxw[48];
    __shared__ float shu[48];
    int g = blockIdx.x;
    int c = threadIdx.x;  // 80
    if (c < 32)      sx[c] = asum[g * 32 + c];
    else if (c < 64) sx[c] = esum[g * 32 + (c - 32)];
    else             sx[c] = s_in[g * 16 + (c - 64)];
    if (c < 16) shh[c] = s_in[g * 16 + c];
    __syncthreads();
    if (c < 48) {
        float xw = bsin[c], hu = bsrec[c];
        for (int k = 0; k < 80; k++) xw += sx[k] * Ws[k * 48 + c];
        for (int k = 0; k < 16; k++) hu += shh[k] * Us[k * 48 + c];
        sxw[c] = xw; shu[c] = hu;
    }
    __syncthreads();
    if (c < 16) {
        float z = sigm(sxw[c] + shu[c]);
        float r = sigm(sxw[16 + c] + shu[16 + c]);
        float hc = tanhf(sxw[32 + c] + r * shu[32 + c]);
        s_out[g * 16 + c] = z * shh[c] + (1.f - z) * hc;
    }
}

// ---------------- host orchestration (fully serial, minimal graph nodes) -----
extern "C" void kernel_launch(void* const* d_in, const int* in_sizes, int n_in,
                              void* d_out, int out_size) {
    const float* a0    = (const float*)d_in[0];
    const float* e0    = (const float*)d_in[1];
    const float* s0    = (const float*)d_in[2];
    const int*   pair  = (const int*)d_in[3];
    const int*   agi   = (const int*)d_in[4];
    const int*   bgi   = (const int*)d_in[5];
    const float* kern  = (const float*)d_in[6];
    const float* bias  = (const float*)d_in[7];
    const float* We    = (const float*)d_in[8];
    const float* Ue    = (const float*)d_in[9];
    const float* bein  = (const float*)d_in[10];
    const float* berec = (const float*)d_in[11];
    const float* Wn    = (const float*)d_in[12];
    const float* Un    = (const float*)d_in[13];
    const float* bnin  = (const float*)d_in[14];
    const float* bnrec = (const float*)d_in[15];
    const float* Ws    = (const float*)d_in[16];
    const float* Us    = (const float*)d_in[17];
    const float* bsin  = (const float*)d_in[18];
    const float* bsrec = (const float*)d_in[19];
    float* out = (float*)d_out;

    float *ga, *ge, *gs, *gv, *gagg, *gas, *ges, *gw3, *gpau, *gs3;
    unsigned *gwt32, *gw2;
    cudaGetSymbolAddress((void**)&ga,    g_a);
    cudaGetSymbolAddress((void**)&ge,    g_e);
    cudaGetSymbolAddress((void**)&gs,    g_s);
    cudaGetSymbolAddress((void**)&gv,    g_v);
    cudaGetSymbolAddress((void**)&gwt32, g_wt32);
    cudaGetSymbolAddress((void**)&gagg,  g_agg);
    cudaGetSymbolAddress((void**)&gas,   g_asum);
    cudaGetSymbolAddress((void**)&ges,   g_esum);
    cudaGetSymbolAddress((void**)&gw2,   g_wcat2);
    cudaGetSymbolAddress((void**)&gw3,   g_wcat3);
    cudaGetSymbolAddress((void**)&gpau,  g_pau);
    cudaGetSymbolAddress((void**)&gs3,   g_s3);

    static bool s_init = false;
    const int EDGE_SMEM = 64 * 196 * 4;   // 50176 bytes
    if (!s_init) {
        cudaFuncSetAttribute(edge_fused_kernel,
                             cudaFuncAttributeMaxDynamicSharedMemorySize, EDGE_SMEM);
        s_init = true;
    }

    build_weights_kernel<<<(48 * VC + 255) / 256, 256>>>(kern, bias, We, Ue, Un,
                                                         gwt32, gw2, gw3);

    float* oa[2] = {ga, out};
    float* oe[2] = {ge, out + NN * 32};
    float* os[2] = {gs, out + NN * 32 + NE * 32};
    const float* ia = a0;
    const float* ie = e0;
    const float* is_ = s0;

    for (int step = 0; step < 2; step++) {
        front_kernel<<<NBV + NBP, 288>>>(ia, is_, agi, gwt32, gv, gagg,
                                         gw3, We + 64 * 96, gpau, gs3, ges, gas);
        edge_fused_kernel<<<NE / 64, 256, EDGE_SMEM>>>(
            ie, gw2, pair, bgi, gpau, gs3, bein, berec, oe[step], ges);
        scatter_kernel<<<(NE / EPW + 7) / 8, 256>>>(oe[step], pair, gv, gagg);
        node_fused_kernel<<<NN / 16, 96>>>(gagg, Wn, gpau, ia, agi,
                                           bnin, bnrec, oa[step], gas);
        state_gru_kernel<<<NG, 80>>>(gas, ges, is_, Ws, Us, bsin, bsrec, os[step]);

        ia = oa[step]; ie = oe[step]; is_ = os[step];
    }
}

// round 17
// speedup vs baseline: 1.2656x; 1.0053x over previous
#include <cuda_runtime.h>
#include <math.h>

#define NN 10000
#define NE 40000
#define NG 128
#define VC 1584   // 32*48 kernel cols + 48 bias cols

// ---------------- scratch (static device globals; no runtime alloc) ----------
__device__ float    g_a[NN * 32];
__device__ float    g_e[NE * 32];
__device__ float    g_s[NG * 16];
__device__ float    g_v[NN * VC];      // 63.4 MB
__device__ unsigned g_wt32[48 * VC];   // transposed kernel+bias, tf32 bits
__device__ float    g_agg[NN * 48];
__device__ float    g_asum[NG * 32];
__device__ float    g_esum[NG * 32];
__device__ unsigned g_wcat2[32 * 192]; // [We rows 80:112 | Ue], tf32 bits
__device__ float    g_wcat3[32 * 288]; // [We rows 0:32 | We rows 32:64 | Un]
__device__ float    g_pau[NN * 288];   // a @ wcat3
__device__ float    g_s3[NG * 96];     // s @ We rows 64:80
__device__ int      g_hist[NN];        // dst histogram
__device__ int      g_ofs[NN];         // dst offsets (mutated by place)
__device__ int      g_psrc[NE];        // dst-sorted: src per slot
__device__ int      g_pdst[NE];        // dst-sorted: dst per slot
__device__ int      g_peid[NE];        // dst-sorted: original edge id

__device__ __forceinline__ float sigm(float x) { return 1.f / (1.f + expf(-x)); }

__device__ __forceinline__ unsigned f2tf(float f) {
    unsigned u;
    asm("cvt.rna.tf32.f32 %0, %1;" : "=r"(u) : "f"(f));
    return u;
}
__device__ __forceinline__ void mma_tf32(float c[4],
                                         unsigned a0, unsigned a1,
                                         unsigned a2, unsigned a3,
                                         unsigned b0, unsigned b1) {
    asm volatile(
        "mma.sync.aligned.m16n8k8.row.col.f32.tf32.tf32.f32 "
        "{%0,%1,%2,%3}, {%4,%5,%6,%7}, {%8,%9}, {%0,%1,%2,%3};"
        : "+f"(c[0]), "+f"(c[1]), "+f"(c[2]), "+f"(c[3])
        : "r"(a0), "r"(a1), "r"(a2), "r"(a3), "r"(b0), "r"(b1));
}

// ---------------- weight prep (also zeroes dst histogram) --------------------
__global__ void build_weights_kernel(const float* __restrict__ kern,
                                     const float* __restrict__ bias,
                                     const float* __restrict__ We,
                                     const float* __restrict__ Ue,
                                     const float* __restrict__ Un,
                                     unsigned* __restrict__ wt32,
                                     unsigned* __restrict__ wcat2,
                                     float* __restrict__ wcat3,
                                     int* __restrict__ hist) {
    int idx = blockIdx.x * blockDim.x + threadIdx.x;
    if (idx < NN) hist[idx] = 0;
    if (idx < 48 * VC) {
        int j = idx / VC, ki = idx % VC;
        float val = (ki < 1536) ? kern[ki * 48 + j] : bias[(ki - 1536) * 48 + j];
        wt32[idx] = f2tf(val);
    }
    if (idx < 32 * 192) {
        int k = idx / 192, c = idx % 192;
        wcat2[idx] = f2tf((c < 96) ? We[(80 + k) * 96 + c] : Ue[k * 96 + (c - 96)]);
    }
    if (idx < 32 * 288) {
        int k = idx / 288, c = idx % 288;
        float val;
        if (c < 96)       val = We[k * 96 + c];
        else if (c < 192) val = We[(32 + k) * 96 + (c - 96)];
        else              val = Un[k * 96 + (c - 192)];
        wcat3[idx] = val;
    }
}

// ---------------- counting sort of edges by dst (pair is constant) -----------
__global__ void hist_kernel(const int* __restrict__ pair, int* __restrict__ hist) {
    int e = blockIdx.x * blockDim.x + threadIdx.x;
    if (e < NE) atomicAdd(&hist[pair[2 * e + 1]], 1);
}

__global__ void scan_kernel(const int* __restrict__ hist, int* __restrict__ ofs) {
    __shared__ int part[256];
    int t = threadIdx.x;
    int base = t * 40;               // 256*40 = 10240 >= NN
    int sum = 0;
    for (int i = 0; i < 40; i++) {
        int idx = base + i;
        if (idx < NN) sum += hist[idx];
    }
    part[t] = sum;
    __syncthreads();
    if (t == 0) {
        int run = 0;
        for (int i = 0; i < 256; i++) { int v = part[i]; part[i] = run; run += v; }
    }
    __syncthreads();
    int run = part[t];
    for (int i = 0; i < 40; i++) {
        int idx = base + i;
        if (idx < NN) { int v = hist[idx]; ofs[idx] = run; run += v; }
    }
}

__global__ void place_kernel(const int* __restrict__ pair, int* __restrict__ ofs,
                             int* __restrict__ psrc, int* __restrict__ pdst,
                             int* __restrict__ peid) {
    int e = blockIdx.x * blockDim.x + threadIdx.x;
    if (e >= NE) return;
    int src = pair[2 * e], dst = pair[2 * e + 1];
    int pos = atomicAdd(&ofs[dst], 1);
    psrc[pos] = src; pdst[pos] = dst; peid[pos] = e;
}

// ---------------- v = [a | s[agi]] @ wt (tf32, K=48); also zeroes agg --------
__global__ __launch_bounds__(256)
void compute_v_fused(const float* __restrict__ a, const float* __restrict__ s,
                     const int* __restrict__ agi, const unsigned* __restrict__ wt32,
                     float* __restrict__ v, float* __restrict__ agg) {
    __shared__ __align__(16) char raw[(64 * 52 + 48 * 132) * 4];
    unsigned* sA = (unsigned*)raw;               // 64 x 52
    unsigned* sB = (unsigned*)raw + 64 * 52;     // 48 x 132
    float* sC = (float*)raw;                     // 64 x 132 (reused)
    __shared__ int s_gi[64];
    int m0 = blockIdx.y * 64;
    int n0 = blockIdx.x * 128;
    int tid = threadIdx.x;

    {   // zero agg chunk: 2041 blocks x 236 covers NN*48
        int bid = blockIdx.y * gridDim.x + blockIdx.x;
        int z = bid * 236 + tid;
        if (tid < 236 && z < NN * 48) agg[z] = 0.f;
    }
    if (tid < 64) s_gi[tid] = (m0 + tid < NN) ? agi[m0 + tid] : 0;
    __syncthreads();

    for (int i = tid; i < 64 * 32; i += 256) {
        int r = i >> 5, k = i & 31;
        float val = (m0 + r < NN) ? a[(size_t)(m0 + r) * 32 + k] : 0.f;
        sA[r * 52 + k] = f2tf(val);
    }
    for (int i = tid; i < 64 * 16; i += 256) {
        int r = i >> 4, k = i & 15;
        float val = (m0 + r < NN) ? s[s_gi[r] * 16 + k] : 0.f;
        sA[r * 52 + 32 + k] = f2tf(val);
    }
    for (int i = tid; i < 48 * 128; i += 256) {
        int k = i >> 7, n = i & 127;
        sB[k * 132 + n] = (n0 + n < VC) ? wt32[(size_t)k * VC + n0 + n] : 0u;
    }
    __syncthreads();

    int wid = tid >> 5, lane = tid & 31;
    int wm = wid & 3, wn = wid >> 2;
    int lq = lane >> 2, lr = lane & 3;

    float c[8][4];
#pragma unroll
    for (int nf = 0; nf < 8; nf++)
#pragma unroll
        for (int i = 0; i < 4; i++) c[nf][i] = 0.f;

#pragma unroll
    for (int ks = 0; ks < 6; ks++) {
        int ar = wm * 16 + lq;
        int ac = ks * 8 + lr;
        unsigned a0 = sA[ar * 52 + ac];
        unsigned a1 = sA[(ar + 8) * 52 + ac];
        unsigned a2 = sA[ar * 52 + ac + 4];
        unsigned a3 = sA[(ar + 8) * 52 + ac + 4];
#pragma unroll
        for (int nf = 0; nf < 8; nf++) {
            int bn = wn * 64 + nf * 8 + lq;
            unsigned b0 = sB[(ks * 8 + lr) * 132 + bn];
            unsigned b1 = sB[(ks * 8 + 4 + lr) * 132 + bn];
            mma_tf32(c[nf], a0, a1, a2, a3, b0, b1);
        }
    }
    __syncthreads();

    int row_l = wm * 16 + lq;
    int cb = wn * 64 + lr * 2;
#pragma unroll
    for (int nf = 0; nf < 8; nf++) {
        int col = cb + nf * 8;
        *(float2*)&sC[row_l * 132 + col] = make_float2(c[nf][0], c[nf][1]);
        *(float2*)&sC[(row_l + 8) * 132 + col] = make_float2(c[nf][2], c[nf][3]);
    }
    __syncthreads();

    for (int i = tid; i < 64 * 32; i += 256) {
        int r = i >> 5, c4 = i & 31;
        int row = m0 + r;
        int col = n0 + c4 * 4;
        if (row >= NN || col >= VC) continue;
        *(float4*)&v[(size_t)row * VC + col] = *(float4*)&sC[r * 132 + c4 * 4];
    }
}

// ---------------- pau GEMM + s3 + zero esum/asum -----------------------------
__global__ __launch_bounds__(288)
void pau_s3_kernel(const float* __restrict__ a, const float* __restrict__ W,
                   const float* __restrict__ Ws3, const float* __restrict__ s,
                   float* __restrict__ pau, float* __restrict__ s3,
                   float* __restrict__ esum, float* __restrict__ asum) {
    __shared__ float sW[32 * 288];
    __shared__ __align__(16) float sx[16 * 32];
    int tid = threadIdx.x;
    int bid = blockIdx.x;

    if (bid < 32 && tid < 256) {
        int z = bid * 256 + tid;
        if (z < NG * 32) esum[z] = 0.f;
        else asum[z - NG * 32] = 0.f;
    }
    if (bid == 625) {
        for (int i = tid; i < NG * 16; i += 288) sW[i] = s[i];
        __syncthreads();
        if (tid < 96) {
            for (int g = 0; g < NG; g++) {
                float acc = 0.f;
#pragma unroll
                for (int k = 0; k < 16; k++)
                    acc += sW[g * 16 + k] * Ws3[k * 96 + tid];
                s3[g * 96 + tid] = acc;
            }
        }
        return;
    }

    int base = bid * 16;
#pragma unroll
    for (int k = 0; k < 32; k++) sW[k * 288 + tid] = W[k * 288 + tid];
    for (int i = tid; i < 16 * 32; i += 288) sx[i] = a[(size_t)base * 32 + i];
    __syncthreads();

    float acc[16];
#pragma unroll
    for (int r = 0; r < 16; r++) acc[r] = 0.f;
    const float4* sx4 = (const float4*)sx;
#pragma unroll
    for (int k4 = 0; k4 < 8; k4++) {
        float w0 = sW[(4 * k4 + 0) * 288 + tid];
        float w1 = sW[(4 * k4 + 1) * 288 + tid];
        float w2 = sW[(4 * k4 + 2) * 288 + tid];
        float w3 = sW[(4 * k4 + 3) * 288 + tid];
#pragma unroll
        for (int r = 0; r < 16; r++) {
            float4 xv = sx4[r * 8 + k4];
            acc[r] += w0 * xv.x; acc[r] += w1 * xv.y;
            acc[r] += w2 * xv.z; acc[r] += w3 * xv.w;
        }
    }
#pragma unroll
    for (int r = 0; r < 16; r++)
        pau[(size_t)(base + r) * 288 + tid] = acc[r];
}

// ---------------- fused edge kernel: ew MMA + GRU finalize -------------------
__global__ __launch_bounds__(256)
void edge_fused_kernel(const float* __restrict__ e_in,
                       const unsigned* __restrict__ W,
                       const int* __restrict__ pair,
                       const int* __restrict__ bgi,
                       const float* __restrict__ pau,
                       const float* __restrict__ s3,
                       const float* __restrict__ bin,
                       const float* __restrict__ brec,
                       float* __restrict__ e_out,
                       float* __restrict__ esum) {
    extern __shared__ __align__(16) char dynsm[];
    unsigned* sA = (unsigned*)dynsm;               // 64*33
    unsigned* sB = (unsigned*)dynsm + 64 * 33;     // 32*196
    float* sC = (float*)dynsm;                     // 64*196 (reused)
    __shared__ int sSrc[64], sDst[64], sBg[64];
    int m0 = blockIdx.x * 64;
    int tid = threadIdx.x;

    for (int i = tid; i < 64 * 32; i += 256) {
        int r = i >> 5, k = i & 31;
        sA[r * 33 + k] = f2tf(e_in[(size_t)(m0 + r) * 32 + k]);
    }
    for (int i = tid; i < 32 * 192; i += 256) {
        int k = i / 192, n = i % 192;
        sB[k * 196 + n] = W[k * 192 + n];
    }
    if (tid < 64) {
        int e = m0 + tid;
        sSrc[tid] = pair[2 * e];
        sDst[tid] = pair[2 * e + 1];
        sBg[tid]  = bgi[e];
    }
    __syncthreads();

    int wid = tid >> 5, lane = tid & 31;
    int wm = wid & 3, wn = wid >> 2;
    int lq = lane >> 2, lr = lane & 3;

    float c[12][4];
#pragma unroll
    for (int nf = 0; nf < 12; nf++)
#pragma unroll
        for (int i = 0; i < 4; i++) c[nf][i] = 0.f;

#pragma unroll
    for (int ks = 0; ks < 4; ks++) {
        int ar = wm * 16 + lq;
        int ac = ks * 8 + lr;
        unsigned a0 = sA[ar * 33 + ac];
        unsigned a1 = sA[(ar + 8) * 33 + ac];
        unsigned a2 = sA[ar * 33 + ac + 4];
        unsigned a3 = sA[(ar + 8) * 33 + ac + 4];
#pragma unroll
        for (int nf = 0; nf < 12; nf++) {
            int bn = wn * 96 + nf * 8 + lq;
            unsigned b0 = sB[(ks * 8 + lr) * 196 + bn];
            unsigned b1 = sB[(ks * 8 + 4 + lr) * 196 + bn];
            mma_tf32(c[nf], a0, a1, a2, a3, b0, b1);
        }
    }
    __syncthreads();

    int row_l = wm * 16 + lq;
#pragma unroll
    for (int nf = 0; nf < 12; nf++) {
        int col = wn * 96 + nf * 8 + lr * 2;
        *(float2*)&sC[row_l * 196 + col] = make_float2(c[nf][0], c[nf][1]);
        *(float2*)&sC[(row_l + 8) * 196 + col] = make_float2(c[nf][2], c[nf][3]);
    }
    __syncthreads();

    for (int idx = tid; idx < 64 * 32; idx += 256) {
        int el = idx >> 5, j = idx & 31;
        int e = m0 + el;
        int src = sSrc[el], dst = sDst[el], g = sBg[el];
        const float* pA = pau + (size_t)src * 288;
        const float* pB = pau + (size_t)dst * 288 + 96;
        const float* pS = s3 + g * 96;
        const float* pE = sC + el * 196;
        float xz = pA[j]      + pB[j]      + pS[j]      + pE[j]      + bin[j];
        float xr = pA[32 + j] + pB[32 + j] + pS[32 + j] + pE[32 + j] + bin[32 + j];
        float xh = pA[64 + j] + pB[64 + j] + pS[64 + j] + pE[64 + j] + bin[64 + j];
        float hz = pE[96 + j]  + brec[j];
        float hr = pE[128 + j] + brec[32 + j];
        float hh = pE[160 + j] + brec[64 + j];
        float h  = e_in[(size_t)e * 32 + j];
        float z  = sigm(xz + hz);
        float r  = sigm(xr + hr);
        float hc = tanhf(xh + r * hh);
        float val = z * h + (1.f - z) * hc;
        e_out[(size_t)e * 32 + j] = val;
        atomicAdd(&esum[g * 32 + j], val);
    }
}

// ---------------- scatter over dst-sorted slots (L1 reuse of v rows) ---------
#define EPW 8
__global__ __launch_bounds__(256)
void scatter_kernel(const float* __restrict__ e_feat,
                    const int* __restrict__ psrc,
                    const int* __restrict__ pdst,
                    const int* __restrict__ peid,
                    const float* __restrict__ v,
                    float* __restrict__ agg) {
    int lane = threadIdx.x & 31;
    int warp = (blockIdx.x * blockDim.x + threadIdx.x) >> 5;
    int s0 = warp * EPW;
    if (s0 >= NE) return;
    int send = min(s0 + EPW, NE);
    for (int sl = s0; sl < send; sl++) {
        int e   = __ldg(&peid[sl]);
        int src = __ldg(&psrc[sl]);
        int dst = __ldg(&pdst[sl]);
        const float* vp = v + (size_t)dst * VC;
        float ev = __ldg(&e_feat[(size_t)e * 32 + lane]);
        float acc0 = __ldg(&vp[1536 + lane]);
        float acc1 = (lane < 16) ? __ldg(&vp[1568 + lane]) : 0.f;
#pragma unroll
        for (int k = 0; k < 32; k++) {
            float ek = __shfl_sync(0xffffffffu, ev, k);
            acc0 += ek * __ldg(&vp[k * 48 + lane]);
            if (lane < 16) acc1 += ek * __ldg(&vp[k * 48 + 32 + lane]);
        }
        atomicAdd(&agg[src * 48 + lane], acc0);
        if (lane < 16) atomicAdd(&agg[src * 48 + 32 + lane], acc1);
    }
}

// ---------------- fused node kernel: agg@Wn GEMM + GRU finalize --------------
__global__ __launch_bounds__(96)
void node_fused_kernel(const float* __restrict__ agg,
                       const float* __restrict__ Wn,
                       const float* __restrict__ pau,
                       const float* __restrict__ a_in,
                       const int* __restrict__ agi,
                       const float* __restrict__ bin,
                       const float* __restrict__ brec,
                       float* __restrict__ a_out,
                       float* __restrict__ asum) {
    __shared__ float sW[48 * 96];
    __shared__ __align__(16) float sx[16 * 48];
    __shared__ float sxw[16 * 96];
    __shared__ int sgi[16];
    int tid = threadIdx.x;
    int base = blockIdx.x * 16;

    for (int i = tid; i < 48 * 96; i += 96) sW[i] = Wn[i];
    for (int i = tid; i < 16 * 48; i += 96) sx[i] = agg[(size_t)base * 48 + i];
    if (tid < 16) sgi[tid] = agi[base + tid];
    __syncthreads();

    float acc[16];
#pragma unroll
    for (int r = 0; r < 16; r++) acc[r] = 0.f;
    const float4* sx4 = (const float4*)sx;
#pragma unroll
    for (int k4 = 0; k4 < 12; k4++) {
        float w0 = sW[(4 * k4 + 0) * 96 + tid];
        float w1 = sW[(4 * k4 + 1) * 96 + tid];
        float w2 = sW[(4 * k4 + 2) * 96 + tid];
        float w3 = sW[(4 * k4 + 3) * 96 + tid];
#pragma unroll
        for (int r = 0; r < 16; r++) {
            float4 xv = sx4[r * 12 + k4];
            acc[r] += w0 * xv.x; acc[r] += w1 * xv.y;
            acc[r] += w2 * xv.z; acc[r] += w3 * xv.w;
        }
    }
#pragma unroll
    for (int r = 0; r < 16; r++) sxw[r * 96 + tid] = acc[r];
    __syncthreads();

    for (int idx = tid; idx < 16 * 32; idx += 96) {
        int nl = idx >> 5, j = idx & 31;
        int n = base + nl;
        const float* pH = pau + (size_t)n * 288 + 192;
        float xz = sxw[nl * 96 + j]      + bin[j];
        float xr = sxw[nl * 96 + 32 + j] + bin[32 + j];
        float xh = sxw[nl * 96 + 64 + j] + bin[64 + j];
        float hz = pH[j]      + brec[j];
        float hr = pH[32 + j] + brec[32 + j];
        float hh = pH[64 + j] + brec[64 + j];
        float h  = a_in[(size_t)n * 32 + j];
        float z  = sigm(xz + hz);
        float r  = sigm(xr + hr);
        float hc = tanhf(xh + r * hh);
        float val = z * h + (1.f - z) * hc;
        a_out[(size_t)n * 32 + j] = val;
        atomicAdd(&asum[sgi[nl] * 32 + j], val);
    }
}

// ---------------- state GRU: s = GRU([asum, esum, s], s) ---------------------
__global__ void state_gru_kernel(
    const float* __restrict__ asum, const float* __restrict__ esum,
    const float* __restrict__ s_in,
    const float* __restrict__ Ws, const float* __restrict__ Us,
    const float* __restrict__ bsin, const float* __restrict__ bsrec,
    float* __restrict__ s_out) {
    __shared__ float sx[80];
    __shared__ float shh[16];
    __shared__ float sxw[48];
    __shared__ float shu[48];
    int g = blockIdx.x;
    int c = threadIdx.x;  // 80
    if (c < 32)      sx[c] = asum[g * 32 + c];
    else if (c < 64) sx[c] = esum[g * 32 + (c - 32)];
    else             sx[c] = s_in[g * 16 + (c - 64)];
    if (c < 16) shh[c] = s_in[g * 16 + c];
    __syncthreads();
    if (c < 48) {
        float xw = bsin[c], hu = bsrec[c];
        for (int k = 0; k < 80; k++) xw += sx[k] * Ws[k * 48 + c];
        for (int k = 0; k < 16; k++) hu += shh[k] * Us[k * 48 + c];
        sxw[c] = xw; shu[c] = hu;
    }
    __syncthreads();
    if (c < 16) {
        float z = sigm(sxw[c] + shu[c]);
        float r = sigm(sxw[16 + c] + shu[16 + c]);
        float hc = tanhf(sxw[32 + c] + r * shu[32 + c]);
        s_out[g * 16 + c] = z * shh[c] + (1.f - z) * hc;
    }
}

// ---------------- host orchestration -----------------------------------------
extern "C" void kernel_launch(void* const* d_in, const int* in_sizes, int n_in,
                              void* d_out, int out_size) {
    const float* a0    = (const float*)d_in[0];
    const float* e0    = (const float*)d_in[1];
    const float* s0    = (const float*)d_in[2];
    const int*   pair  = (const int*)d_in[3];
    const int*   agi   = (const int*)d_in[4];
    const int*   bgi   = (const int*)d_in[5];
    const float* kern  = (const float*)d_in[6];
    const float* bias  = (const float*)d_in[7];
    const float* We    = (const float*)d_in[8];
    const float* Ue    = (const float*)d_in[9];
    const float* bein  = (const float*)d_in[10];
    const float* berec = (const float*)d_in[11];
    const float* Wn    = (const float*)d_in[12];
    const float* Un    = (const float*)d_in[13];
    const float* bnin  = (const float*)d_in[14];
    const float* bnrec = (const float*)d_in[15];
    const float* Ws    = (const float*)d_in[16];
    const float* Us    = (const float*)d_in[17];
    const float* bsin  = (const float*)d_in[18];
    const float* bsrec = (const float*)d_in[19];
    float* out = (float*)d_out;

    float *ga, *ge, *gs, *gv, *gagg, *gas, *ges, *gw3, *gpau, *gs3;
    unsigned *gwt32, *gw2;
    int *ghist, *gofs, *gpsrc, *gpdst, *gpeid;
    cudaGetSymbolAddress((void**)&ga,    g_a);
    cudaGetSymbolAddress((void**)&ge,    g_e);
    cudaGetSymbolAddress((void**)&gs,    g_s);
    cudaGetSymbolAddress((void**)&gv,    g_v);
    cudaGetSymbolAddress((void**)&gwt32, g_wt32);
    cudaGetSymbolAddress((void**)&gagg,  g_agg);
    cudaGetSymbolAddress((void**)&gas,   g_asum);
    cudaGetSymbolAddress((void**)&ges,   g_esum);
    cudaGetSymbolAddress((void**)&gw2,   g_wcat2);
    cudaGetSymbolAddress((void**)&gw3,   g_wcat3);
    cudaGetSymbolAddress((void**)&gpau,  g_pau);
    cudaGetSymbolAddress((void**)&gs3,   g_s3);
    cudaGetSymbolAddress((void**)&ghist, g_hist);
    cudaGetSymbolAddress((void**)&gofs,  g_ofs);
    cudaGetSymbolAddress((void**)&gpsrc, g_psrc);
    cudaGetSymbolAddress((void**)&gpdst, g_pdst);
    cudaGetSymbolAddress((void**)&gpeid, g_peid);

    static bool s_init = false;
    static cudaStream_t st2;
    static cudaEvent_t ev0[2], evE[2], evS;
    const int EDGE_SMEM = 64 * 196 * 4;   // 50176 bytes
    if (!s_init) {
        cudaStreamCreateWithFlags(&st2, cudaStreamNonBlocking);
        for (int i = 0; i < 2; i++) {
            cudaEventCreateWithFlags(&ev0[i], cudaEventDisableTiming);
            cudaEventCreateWithFlags(&evE[i], cudaEventDisableTiming);
        }
        cudaEventCreateWithFlags(&evS, cudaEventDisableTiming);
        cudaFuncSetAttribute(edge_fused_kernel,
                             cudaFuncAttributeMaxDynamicSharedMemorySize, EDGE_SMEM);
        s_init = true;
    }

    // prologue: weights (+hist zero), then dst-sort of edges on st2
    build_weights_kernel<<<(48 * VC + 255) / 256, 256>>>(
        kern, bias, We, Ue, Un, gwt32, gw2, gw3, ghist);
    cudaEventRecord(evS, 0);
    cudaStreamWaitEvent(st2, evS, 0);
    hist_kernel<<<(NE + 255) / 256, 256, 0, st2>>>(pair, ghist);
    scan_kernel<<<1, 256, 0, st2>>>(ghist, gofs);
    place_kernel<<<(NE + 255) / 256, 256, 0, st2>>>(pair, gofs, gpsrc, gpdst, gpeid);

    float* oa[2] = {ga, out};
    float* oe[2] = {ge, out + NN * 32};
    float* os[2] = {gs, out + NN * 32 + NE * 32};
    const float* ia = a0;
    const float* ie = e0;
    const float* is_ = s0;

    for (int step = 0; step < 2; step++) {
        cudaEventRecord(ev0[step], 0);

        // main: v GEMM (also zeroes agg)
        compute_v_fused<<<dim3(13, 157), 256>>>(ia, is_, agi, gwt32, gv, gagg);

        // st2: pau+s3 (+zero esum/asum), then fused edge MMA+GRU
        cudaStreamWaitEvent(st2, ev0[step], 0);
        pau_s3_kernel<<<626, 288, 0, st2>>>(ia, gw3, We + 64 * 96, is_,
                                            gpau, gs3, ges, gas);
        edge_fused_kernel<<<NE / 64, 256, EDGE_SMEM, st2>>>(
            ie, gw2, pair, bgi, gpau, gs3, bein, berec, oe[step], ges);
        cudaEventRecord(evE[step], st2);

        // main: join, dst-sorted scatter, fused node GRU, state GRU
        cudaStreamWaitEvent(0, evE[step], 0);
        scatter_kernel<<<(NE / EPW + 7) / 8, 256>>>(oe[step], gpsrc, gpdst,
                                                    gpeid, gv, gagg);
        node_fused_kernel<<<NN / 16, 96>>>(gagg, Wn, gpau, ia, agi,
                                           bnin, bnrec, oa[step], gas);
        state_gru_kernel<<<NG, 80>>>(gas, ges, is_, Ws, Us, bsin, bsrec, os[step]);

        ia = oa[step]; ie = oe[step]; is_ = os[step];
    }
}